// round 2
// baseline (speedup 1.0000x reference)
#include <cuda_runtime.h>

#define HID   1024
#define NHEAD 16
#define HD    64
#define BATCH 2
#define SEQ   2048
#define BH    (BATCH*NHEAD)          // 32
#define MR    (BATCH*SEQ)            // 4096
#define QKVSZ (BH*SEQ*HD)            // 4194304 floats per Q/K/V

// Scratch (device globals -- no allocation allowed)
__device__ float g_qkv[3*QKVSZ];     // Q | K | V, each [b,h,s,d]
__device__ float g_ctx[MR*HID];      // attention output [b,s,h*d]

// ---------------------------------------------------------------------------
// Tiled SGEMM:  C[M,N] = A[M,K] * W[N,K]^T + bias[N]
// BM=BN=128, BK=16, 256 threads, 8x8 per thread (split 4+4 ownership so smem
// reads are float4 with <=2-way conflicts).
// MODE 0: A = x, scatter result into g_qkv with [b,h,s,d] layout
// MODE 1: A = g_ctx, plain row-major write into C
// ---------------------------------------------------------------------------
template<int MODE>
__global__ __launch_bounds__(256)
void sgemm_nt(const float* __restrict__ A, const float* __restrict__ W,
              const float* __restrict__ bias, float* __restrict__ C,
              int Kd, int Nd)
{
    __shared__ float As[16][132];
    __shared__ float Bs[16][132];
    const int tid = threadIdx.x;
    const int tx = tid & 15, ty = tid >> 4;
    const int m0 = blockIdx.y << 7;
    const int n0 = blockIdx.x << 7;
    const float* Ap = (MODE == 1) ? (const float*)g_ctx : A;

    float acc[8][8];
#pragma unroll
    for (int i = 0; i < 8; i++)
#pragma unroll
        for (int j = 0; j < 8; j++) acc[i][j] = 0.f;

    for (int k0 = 0; k0 < Kd; k0 += 16) {
#pragma unroll
        for (int it = 0; it < 2; it++) {
            int idx = tid + it * 256;
            int row = idx >> 2, c4 = (idx & 3) << 2;
            float4 va = *(const float4*)(Ap + (m0 + row) * Kd + k0 + c4);
            As[c4+0][row] = va.x; As[c4+1][row] = va.y;
            As[c4+2][row] = va.z; As[c4+3][row] = va.w;
            float4 vb = *(const float4*)(W + (n0 + row) * Kd + k0 + c4);
            Bs[c4+0][row] = vb.x; Bs[c4+1][row] = vb.y;
            Bs[c4+2][row] = vb.z; Bs[c4+3][row] = vb.w;
        }
        __syncthreads();
#pragma unroll
        for (int k = 0; k < 16; k++) {
            float a[8], b[8];
            *(float4*)&a[0] = *(const float4*)&As[k][ty*4];
            *(float4*)&a[4] = *(const float4*)&As[k][64 + ty*4];
            *(float4*)&b[0] = *(const float4*)&Bs[k][tx*4];
            *(float4*)&b[4] = *(const float4*)&Bs[k][64 + tx*4];
#pragma unroll
            for (int i = 0; i < 8; i++)
#pragma unroll
                for (int j = 0; j < 8; j++)
                    acc[i][j] = fmaf(a[i], b[j], acc[i][j]);
        }
        __syncthreads();
    }

#pragma unroll
    for (int i = 0; i < 8; i++) {
        int m = m0 + ((i < 4) ? (ty*4 + i) : (64 + ty*4 + i - 4));
#pragma unroll
        for (int j = 0; j < 8; j++) {
            int n = n0 + ((j < 4) ? (tx*4 + j) : (64 + tx*4 + j - 4));
            float v = acc[i][j] + bias[n];
            if (MODE == 0) {
                int which = n >> 10;          // 0=Q 1=K 2=V
                int wi = n & 1023;
                int h  = wi >> 6, dd = wi & 63;
                int bb = m >> 11, s = m & 2047;
                g_qkv[which * QKVSZ + (((bb * NHEAD + h) * SEQ + s) << 6) + dd] = v;
            } else {
                C[m * Nd + n] = v;
            }
        }
    }
}

// ---------------------------------------------------------------------------
// Flash attention: one CTA per (q-tile of 64, b*h). 256 threads as 16x16.
// Thread (tx,ty): score rows ty*4+i (i<4), score cols tx and tx+16 (BKV=32),
// output cols tx*4..tx*4+3 (d=64). Row group = 16 contiguous lanes -> shfl.
// ---------------------------------------------------------------------------
__global__ __launch_bounds__(256)
void attn_kernel(const int* __restrict__ mask)
{
    __shared__ float Qs[64][68];
    __shared__ float Ks[32][68];
    __shared__ float Vs[32][68];
    __shared__ float Ps[64][36];
    __shared__ int   msk[32];

    const int tid = threadIdx.x;
    const int tx = tid & 15, ty = tid >> 4;
    const int bh = blockIdx.y;
    const int bb = bh >> 4, h = bh & 15;
    const int q0 = blockIdx.x << 6;

    const float* Qg = g_qkv + bh * (SEQ*HD) + q0 * HD;
    const float* Kg = g_qkv + QKVSZ   + bh * (SEQ*HD);
    const float* Vg = g_qkv + 2*QKVSZ + bh * (SEQ*HD);

#pragma unroll
    for (int it = 0; it < 4; it++) {
        int idx = tid + it * 256;
        int row = idx >> 4, c4 = (idx & 15) << 2;
        *(float4*)&Qs[row][c4] = *(const float4*)(Qg + row*HD + c4);
    }

    float acc[4][4];
    float mrow[4], lrow[4];
#pragma unroll
    for (int i = 0; i < 4; i++) {
        mrow[i] = -1e30f; lrow[i] = 0.f;
#pragma unroll
        for (int j = 0; j < 4; j++) acc[i][j] = 0.f;
    }

    for (int kv0 = 0; kv0 < SEQ; kv0 += 32) {
        __syncthreads();   // protect Ks/Vs/Ps reuse across iterations
#pragma unroll
        for (int it = 0; it < 2; it++) {
            int idx = tid + it*256;
            int row = idx >> 4, c4 = (idx & 15) << 2;
            *(float4*)&Ks[row][c4] = *(const float4*)(Kg + (kv0+row)*HD + c4);
            *(float4*)&Vs[row][c4] = *(const float4*)(Vg + (kv0+row)*HD + c4);
        }
        if (tid < 32) msk[tid] = mask[bb * SEQ + kv0 + tid];
        __syncthreads();

        // S = Q * K^T for this tile
        float s[4][2] = {{0.f,0.f},{0.f,0.f},{0.f,0.f},{0.f,0.f}};
#pragma unroll
        for (int d4 = 0; d4 < 16; d4++) {
            float4 q[4], kk[2];
#pragma unroll
            for (int i = 0; i < 4; i++)
                q[i] = *(const float4*)&Qs[ty*4+i][d4<<2];
            kk[0] = *(const float4*)&Ks[tx][d4<<2];
            kk[1] = *(const float4*)&Ks[tx+16][d4<<2];
#pragma unroll
            for (int i = 0; i < 4; i++)
#pragma unroll
                for (int j = 0; j < 2; j++) {
                    float4 kv = (j == 0) ? kk[0] : kk[1];
                    s[i][j] = fmaf(q[i].x, kv.x, s[i][j]);
                    s[i][j] = fmaf(q[i].y, kv.y, s[i][j]);
                    s[i][j] = fmaf(q[i].z, kv.z, s[i][j]);
                    s[i][j] = fmaf(q[i].w, kv.w, s[i][j]);
                }
        }

        const int mk0 = msk[tx], mk1 = msk[tx+16];
#pragma unroll
        for (int i = 0; i < 4; i++) {
            float s0 = mk0 ? s[i][0]*0.125f : -1e9f;
            float s1 = mk1 ? s[i][1]*0.125f : -1e9f;
            float lm = fmaxf(s0, s1);
#pragma unroll
            for (int off = 8; off >= 1; off >>= 1)
                lm = fmaxf(lm, __shfl_xor_sync(0xffffffffu, lm, off));
            float nm   = fmaxf(mrow[i], lm);
            float corr = __expf(mrow[i] - nm);
            float p0 = __expf(s0 - nm);
            float p1 = __expf(s1 - nm);
            float ls = p0 + p1;
#pragma unroll
            for (int off = 8; off >= 1; off >>= 1)
                ls += __shfl_xor_sync(0xffffffffu, ls, off);
            lrow[i] = lrow[i]*corr + ls;
            mrow[i] = nm;
            acc[i][0]*=corr; acc[i][1]*=corr; acc[i][2]*=corr; acc[i][3]*=corr;
            Ps[ty*4+i][tx]    = p0;
            Ps[ty*4+i][tx+16] = p1;
        }
        __syncthreads();

        // O += P * V
#pragma unroll
        for (int k4 = 0; k4 < 8; k4++) {
            float4 p4[4];
#pragma unroll
            for (int i = 0; i < 4; i++)
                p4[i] = *(const float4*)&Ps[ty*4+i][k4<<2];
#pragma unroll
            for (int qq = 0; qq < 4; qq++) {
                float4 v4 = *(const float4*)&Vs[(k4<<2)+qq][tx<<2];
#pragma unroll
                for (int i = 0; i < 4; i++) {
                    float p = (qq==0)?p4[i].x:(qq==1)?p4[i].y:(qq==2)?p4[i].z:p4[i].w;
                    acc[i][0] = fmaf(p, v4.x, acc[i][0]);
                    acc[i][1] = fmaf(p, v4.y, acc[i][1]);
                    acc[i][2] = fmaf(p, v4.z, acc[i][2]);
                    acc[i][3] = fmaf(p, v4.w, acc[i][3]);
                }
            }
        }
    }

#pragma unroll
    for (int i = 0; i < 4; i++) {
        float inv = 1.0f / lrow[i];
        int qr = q0 + ty*4 + i;
        float4 o;
        o.x = acc[i][0]*inv; o.y = acc[i][1]*inv;
        o.z = acc[i][2]*inv; o.w = acc[i][3]*inv;
        *(float4*)(g_ctx + (bb*SEQ + qr)*HID + h*HD + (tx<<2)) = o;
    }
}

// ---------------------------------------------------------------------------
extern "C" void kernel_launch(void* const* d_in, const int* in_sizes, int n_in,
                              void* d_out, int out_size)
{
    (void)in_sizes; (void)n_in; (void)out_size;
    const float* x      = (const float*)d_in[0];
    const int*   mask   = (const int*)  d_in[1];
    const float* qkv_w  = (const float*)d_in[2];
    const float* qkv_b  = (const float*)d_in[3];
    const float* out_w  = (const float*)d_in[4];
    const float* out_b  = (const float*)d_in[5];

    // 1) QKV projection, scattered into [b,h,s,d] scratch
    sgemm_nt<0><<<dim3(3*HID/128, MR/128), 256>>>(x, qkv_w, qkv_b, nullptr, HID, 3*HID);
    // 2) masked flash attention -> g_ctx [b,s,h*d]
    attn_kernel<<<dim3(SEQ/64, BH), 256>>>(mask);
    // 3) output projection -> d_out
    sgemm_nt<1><<<dim3(HID/128, MR/128), 256>>>(nullptr, out_w, out_b, (float*)d_out, HID, HID);
}

// round 4
// speedup vs baseline: 2.9998x; 2.9998x over previous
#include <cuda_runtime.h>
#include <cstdint>

#define HID   1024
#define NHEAD 16
#define HD    64
#define BATCH 2
#define SEQ   2048
#define BH    (BATCH*NHEAD)          // 32
#define MR    (BATCH*SEQ)            // 4096
#define QKVSZ (BH*SEQ*HD)            // 4194304 floats per tensor

// Scratch (device globals -- no allocation allowed)
__device__ float g_qkv[3*QKVSZ];     // Q | K | V, each [b,h,s,d]
__device__ float g_ctx[MR*HID];      // attention output [b,s,h*d]

// ---------------------------------------------------------------------------
// tf32 warp MMA helpers
// ---------------------------------------------------------------------------
__device__ __forceinline__ uint32_t f2tf32(float x) {
    uint32_t r; asm("cvt.rna.tf32.f32 %0, %1;" : "=r"(r) : "f"(x)); return r;
}
__device__ __forceinline__ void mma_tf32(
    float& d0, float& d1, float& d2, float& d3,
    uint32_t a0, uint32_t a1, uint32_t a2, uint32_t a3,
    uint32_t b0, uint32_t b1)
{
    asm volatile(
        "mma.sync.aligned.m16n8k8.row.col.f32.tf32.tf32.f32 "
        "{%0,%1,%2,%3}, {%4,%5,%6,%7}, {%8,%9}, {%0,%1,%2,%3};"
        : "+f"(d0), "+f"(d1), "+f"(d2), "+f"(d3)
        : "r"(a0), "r"(a1), "r"(a2), "r"(a3), "r"(b0), "r"(b1));
}

// ---------------------------------------------------------------------------
// TF32 tensor-core GEMM: C[M,N] = A[M,K] * W[N,K]^T + bias[N]
// BM=BN=128, BK=32, 256 threads (8 warps as 4x2), warp tile 32x64.
// MODE 0: A = x, scatter into g_qkv [b,h,s,d];  MODE 1: A = g_ctx, C plain.
// ---------------------------------------------------------------------------
template<int MODE>
__global__ __launch_bounds__(256)
void gemm_tc(const float* __restrict__ A, const float* __restrict__ W,
             const float* __restrict__ bias, float* __restrict__ C,
             int Kd, int Nd)
{
    __shared__ uint32_t As[128][36];     // [m][k], pitch 36 -> conflict-free frags
    __shared__ uint32_t Bs[128][36];     // [n][k]

    const int tid  = threadIdx.x;
    const int lane = tid & 31;
    const int wid  = tid >> 5;
    const int g    = lane >> 2;          // group id 0..7
    const int t4   = lane & 3;           // thread-in-group
    const int wm   = wid & 3;            // 4 warps along M (32 rows each)
    const int wn   = wid >> 2;           // 2 warps along N (64 cols each)
    const int m0   = blockIdx.y << 7;
    const int n0   = blockIdx.x << 7;
    const float* Ap = (MODE == 1) ? (const float*)g_ctx : A;

    float acc[2][8][4];
#pragma unroll
    for (int mt = 0; mt < 2; mt++)
#pragma unroll
        for (int nt = 0; nt < 8; nt++)
#pragma unroll
            for (int r = 0; r < 4; r++) acc[mt][nt][r] = 0.f;

    for (int k0 = 0; k0 < Kd; k0 += 32) {
#pragma unroll
        for (int it = 0; it < 4; it++) {
            int idx = tid + (it << 8);
            int row = idx >> 3, q = (idx & 7) << 2;
            float4 va = *(const float4*)(Ap + (m0 + row) * Kd + k0 + q);
            As[row][q+0] = f2tf32(va.x); As[row][q+1] = f2tf32(va.y);
            As[row][q+2] = f2tf32(va.z); As[row][q+3] = f2tf32(va.w);
            float4 vb = *(const float4*)(W + (n0 + row) * Kd + k0 + q);
            Bs[row][q+0] = f2tf32(vb.x); Bs[row][q+1] = f2tf32(vb.y);
            Bs[row][q+2] = f2tf32(vb.z); Bs[row][q+3] = f2tf32(vb.w);
        }
        __syncthreads();
#pragma unroll
        for (int ks = 0; ks < 4; ks++) {
            const int kc = ks << 3;
            uint32_t af[2][4], bf[8][2];
#pragma unroll
            for (int mt = 0; mt < 2; mt++) {
                int r = wm * 32 + mt * 16;
                af[mt][0] = As[r + g    ][kc + t4];
                af[mt][1] = As[r + g + 8][kc + t4];
                af[mt][2] = As[r + g    ][kc + t4 + 4];
                af[mt][3] = As[r + g + 8][kc + t4 + 4];
            }
#pragma unroll
            for (int nt = 0; nt < 8; nt++) {
                int c = wn * 64 + nt * 8 + g;
                bf[nt][0] = Bs[c][kc + t4];
                bf[nt][1] = Bs[c][kc + t4 + 4];
            }
#pragma unroll
            for (int mt = 0; mt < 2; mt++)
#pragma unroll
                for (int nt = 0; nt < 8; nt++)
                    mma_tf32(acc[mt][nt][0], acc[mt][nt][1],
                             acc[mt][nt][2], acc[mt][nt][3],
                             af[mt][0], af[mt][1], af[mt][2], af[mt][3],
                             bf[nt][0], bf[nt][1]);
        }
        __syncthreads();
    }

    // Epilogue: bias + write (c0,c1)=(row g), (c2,c3)=(row g+8), cols 2*t4,+1
#pragma unroll
    for (int mt = 0; mt < 2; mt++) {
        int mA = m0 + wm * 32 + mt * 16 + g;
        int mB = mA + 8;
#pragma unroll
        for (int nt = 0; nt < 8; nt++) {
            int n = n0 + wn * 64 + nt * 8 + 2 * t4;
            float b0 = bias[n], b1 = bias[n + 1];
            float v00 = acc[mt][nt][0] + b0, v01 = acc[mt][nt][1] + b1;
            float v10 = acc[mt][nt][2] + b0, v11 = acc[mt][nt][3] + b1;
            if (MODE == 0) {
                int which = n >> 10;
                int wi = n & 1023;
                int h = wi >> 6, dd = wi & 63;          // dd even, pair in-head
                {
                    int bb = mA >> 11, s = mA & 2047;
                    float* p = g_qkv + which * QKVSZ +
                               (((bb * NHEAD + h) * SEQ + s) << 6) + dd;
                    p[0] = v00; p[1] = v01;
                }
                {
                    int bb = mB >> 11, s = mB & 2047;
                    float* p = g_qkv + which * QKVSZ +
                               (((bb * NHEAD + h) * SEQ + s) << 6) + dd;
                    p[0] = v10; p[1] = v11;
                }
            } else {
                *(float2*)(C + mA * Nd + n) = make_float2(v00, v01);
                *(float2*)(C + mB * Nd + n) = make_float2(v10, v11);
            }
        }
    }
}

// ---------------------------------------------------------------------------
// TF32 tensor-core flash attention.
// CTA: 128 q-rows x full KV sweep (chunks of 32). 8 warps, 16 q-rows each.
// Q fragments register-resident; P routed through warp-private smem.
// ---------------------------------------------------------------------------
__global__ __launch_bounds__(256)
void attn_tc(const int* __restrict__ mask)
{
    __shared__ uint32_t Ks[32][68];      // [kv][d] pitch 68: frag bank = 4g+t4
    __shared__ uint32_t Vs[32][72];      // [kv][d] pitch 72: frag bank = 8*t4+g
    __shared__ uint32_t Ps[8][16 * 36];  // per-warp P 16x32, pitch 36
    __shared__ int msk[32];

    const int tid  = threadIdx.x;
    const int lane = tid & 31;
    const int wid  = tid >> 5;
    const int g    = lane >> 2;
    const int t4   = lane & 3;
    const int bh   = blockIdx.y;
    const int bb   = bh >> 4, h = bh & 15;
    const int q0   = blockIdx.x << 7;
    const int qr   = q0 + wid * 16;

    const float* Qg = g_qkv + bh * (SEQ * HD);
    const float* Kg = Qg + QKVSZ;
    const float* Vg = Qg + 2 * QKVSZ;
    uint32_t* Pw = &Ps[wid][0];

    // Q fragments (16 x 64), tf32, kept in registers
    uint32_t qf[8][4];
#pragma unroll
    for (int kt = 0; kt < 8; kt++) {
        const float* qp = Qg + (qr + g) * HD + kt * 8 + t4;
        qf[kt][0] = f2tf32(qp[0]);
        qf[kt][1] = f2tf32(qp[8 * HD]);
        qf[kt][2] = f2tf32(qp[4]);
        qf[kt][3] = f2tf32(qp[8 * HD + 4]);
    }

    float of[8][4];
#pragma unroll
    for (int nt = 0; nt < 8; nt++)
#pragma unroll
        for (int r = 0; r < 4; r++) of[nt][r] = 0.f;
    float m0r = -1e30f, m1r = -1e30f, l0r = 0.f, l1r = 0.f;

    for (int kv0 = 0; kv0 < SEQ; kv0 += 32) {
        __syncthreads();
#pragma unroll
        for (int it = 0; it < 2; it++) {
            int idx = tid + (it << 8);
            int row = idx >> 4, q = (idx & 15) << 2;
            float4 kk = *(const float4*)(Kg + (kv0 + row) * HD + q);
            Ks[row][q+0] = f2tf32(kk.x); Ks[row][q+1] = f2tf32(kk.y);
            Ks[row][q+2] = f2tf32(kk.z); Ks[row][q+3] = f2tf32(kk.w);
            float4 vv = *(const float4*)(Vg + (kv0 + row) * HD + q);
            Vs[row][q+0] = f2tf32(vv.x); Vs[row][q+1] = f2tf32(vv.y);
            Vs[row][q+2] = f2tf32(vv.z); Vs[row][q+3] = f2tf32(vv.w);
        }
        if (tid < 32) msk[tid] = mask[bb * SEQ + kv0 + tid];
        __syncthreads();

        // S = Q * K^T  (16 x 32 per warp)
        float sf[4][4];
#pragma unroll
        for (int nt = 0; nt < 4; nt++)
#pragma unroll
            for (int r = 0; r < 4; r++) sf[nt][r] = 0.f;
#pragma unroll
        for (int nt = 0; nt < 4; nt++)
#pragma unroll
            for (int kt = 0; kt < 8; kt++) {
                uint32_t b0 = Ks[nt * 8 + g][kt * 8 + t4];
                uint32_t b1 = Ks[nt * 8 + g][kt * 8 + t4 + 4];
                mma_tf32(sf[nt][0], sf[nt][1], sf[nt][2], sf[nt][3],
                         qf[kt][0], qf[kt][1], qf[kt][2], qf[kt][3], b0, b1);
            }

        // Mask + scale + online softmax (rows g and g+8)
        float sm[4][4];
        float lm0 = -1e30f, lm1 = -1e30f;
#pragma unroll
        for (int nt = 0; nt < 4; nt++) {
            int c = nt * 8 + 2 * t4;
            int k0m = msk[c], k1m = msk[c + 1];
            sm[nt][0] = k0m ? sf[nt][0] * 0.125f : -1e9f;
            sm[nt][1] = k1m ? sf[nt][1] * 0.125f : -1e9f;
            sm[nt][2] = k0m ? sf[nt][2] * 0.125f : -1e9f;
            sm[nt][3] = k1m ? sf[nt][3] * 0.125f : -1e9f;
            lm0 = fmaxf(lm0, fmaxf(sm[nt][0], sm[nt][1]));
            lm1 = fmaxf(lm1, fmaxf(sm[nt][2], sm[nt][3]));
        }
        lm0 = fmaxf(lm0, __shfl_xor_sync(0xffffffffu, lm0, 1));
        lm0 = fmaxf(lm0, __shfl_xor_sync(0xffffffffu, lm0, 2));
        lm1 = fmaxf(lm1, __shfl_xor_sync(0xffffffffu, lm1, 1));
        lm1 = fmaxf(lm1, __shfl_xor_sync(0xffffffffu, lm1, 2));

        float nm0 = fmaxf(m0r, lm0), nm1 = fmaxf(m1r, lm1);
        float cr0 = __expf(m0r - nm0), cr1 = __expf(m1r - nm1);
        m0r = nm0; m1r = nm1;

        float ls0 = 0.f, ls1 = 0.f;
#pragma unroll
        for (int nt = 0; nt < 4; nt++) {
            float p00 = __expf(sm[nt][0] - nm0);
            float p01 = __expf(sm[nt][1] - nm0);
            float p10 = __expf(sm[nt][2] - nm1);
            float p11 = __expf(sm[nt][3] - nm1);
            ls0 += p00 + p01; ls1 += p10 + p11;
            int c = nt * 8 + 2 * t4;
            Pw[g * 36 + c]       = f2tf32(p00);
            Pw[g * 36 + c + 1]   = f2tf32(p01);
            Pw[(g + 8) * 36 + c]     = f2tf32(p10);
            Pw[(g + 8) * 36 + c + 1] = f2tf32(p11);
        }
        ls0 += __shfl_xor_sync(0xffffffffu, ls0, 1);
        ls0 += __shfl_xor_sync(0xffffffffu, ls0, 2);
        ls1 += __shfl_xor_sync(0xffffffffu, ls1, 1);
        ls1 += __shfl_xor_sync(0xffffffffu, ls1, 2);
        l0r = l0r * cr0 + ls0;
        l1r = l1r * cr1 + ls1;
#pragma unroll
        for (int nt = 0; nt < 8; nt++) {
            of[nt][0] *= cr0; of[nt][1] *= cr0;
            of[nt][2] *= cr1; of[nt][3] *= cr1;
        }
        __syncwarp();

        // O += P * V
#pragma unroll
        for (int kt = 0; kt < 4; kt++) {
            uint32_t pa0 = Pw[g * 36 + kt * 8 + t4];
            uint32_t pa1 = Pw[(g + 8) * 36 + kt * 8 + t4];
            uint32_t pa2 = Pw[g * 36 + kt * 8 + t4 + 4];
            uint32_t pa3 = Pw[(g + 8) * 36 + kt * 8 + t4 + 4];
#pragma unroll
            for (int nt = 0; nt < 8; nt++) {
                uint32_t b0 = Vs[kt * 8 + t4][nt * 8 + g];
                uint32_t b1 = Vs[kt * 8 + t4 + 4][nt * 8 + g];
                mma_tf32(of[nt][0], of[nt][1], of[nt][2], of[nt][3],
                         pa0, pa1, pa2, pa3, b0, b1);
            }
        }
    }

    // Epilogue: normalize and write [b,s,h*d]
    float inv0 = 1.0f / l0r, inv1 = 1.0f / l1r;
#pragma unroll
    for (int nt = 0; nt < 8; nt++) {
        int c = h * HD + nt * 8 + 2 * t4;
        float* p0 = g_ctx + (bb * SEQ + qr + g) * HID + c;
        float* p1 = g_ctx + (bb * SEQ + qr + g + 8) * HID + c;
        *(float2*)p0 = make_float2(of[nt][0] * inv0, of[nt][1] * inv0);
        *(float2*)p1 = make_float2(of[nt][2] * inv1, of[nt][3] * inv1);
    }
}

// ---------------------------------------------------------------------------
extern "C" void kernel_launch(void* const* d_in, const int* in_sizes, int n_in,
                              void* d_out, int out_size)
{
    (void)in_sizes; (void)n_in; (void)out_size;
    const float* x     = (const float*)d_in[0];
    const int*   mask  = (const int*)  d_in[1];
    const float* qkv_w = (const float*)d_in[2];
    const float* qkv_b = (const float*)d_in[3];
    const float* out_w = (const float*)d_in[4];
    const float* out_b = (const float*)d_in[5];

    gemm_tc<0><<<dim3(3 * HID / 128, MR / 128), 256>>>(x, qkv_w, qkv_b, nullptr, HID, 3 * HID);
    attn_tc<<<dim3(SEQ / 128, BH), 256>>>(mask);
    gemm_tc<1><<<dim3(HID / 128, MR / 128), 256>>>(nullptr, out_w, out_b, (float*)d_out, HID, HID);
}